// round 3
// baseline (speedup 1.0000x reference)
#include <cuda_runtime.h>

// EMD / min-permutation matching on GB300.
//   B=32768, N=6, D=64.
//   cost[b] = (sum of all squared norms) - 2 * maxAssign(G),  G[n][m] = p_n . t_m
//   out[0] = sum_b cost[b]
//
// R3: 4 lanes per batch (16 dims each), dims processed in four 4-float chunks
// to keep register liveness ~80 (6 CTAs/SM). 2-round shfl butterfly; one DP
// pass per warp covers 8 batches.

#define BLOCK 128

__global__ __launch_bounds__(BLOCK, 6)
void emd_kernel(const float* __restrict__ preds,
                const float* __restrict__ targets,
                float* __restrict__ out, int B)
{
    const int g    = blockIdx.x * BLOCK + threadIdx.x;
    const int bRaw = g >> 2;          // batch index
    const int j    = g & 3;           // lane within 4-thread group
    const bool valid = (bRaw < B);
    const int b = valid ? bRaw : (B - 1);   // clamp keeps lanes converged

    const float* pp = preds   + (size_t)b * 384 + 4 * j;
    const float* tt = targets + (size_t)b * 384 + 4 * j;

    float G[36];
#pragma unroll
    for (int i = 0; i < 36; ++i) G[i] = 0.0f;
    float sq = 0.0f;

    // ---- four chunks of 4 dims; 12 LDG.128 in flight per chunk
#pragma unroll 1
    for (int k = 0; k < 4; ++k) {
        const float* pk = pp + k * 16;
        const float* tk = tt + k * 16;

        float4 p[6];
#pragma unroll
        for (int n = 0; n < 6; ++n) p[n] = *(const float4*)(pk + n * 64);

#pragma unroll
        for (int n = 0; n < 6; ++n)
            sq += p[n].x*p[n].x + p[n].y*p[n].y + p[n].z*p[n].z + p[n].w*p[n].w;

#pragma unroll
        for (int m = 0; m < 6; ++m) {
            float4 q = *(const float4*)(tk + m * 64);
            sq += q.x*q.x + q.y*q.y + q.z*q.z + q.w*q.w;
#pragma unroll
            for (int n = 0; n < 6; ++n)
                G[n * 6 + m] += p[n].x*q.x + p[n].y*q.y + p[n].z*q.z + p[n].w*q.w;
        }
    }

    // ---- 2-round butterfly over the 4-lane group
#pragma unroll
    for (int o = 1; o < 4; o <<= 1) {
#pragma unroll
        for (int i = 0; i < 36; ++i)
            G[i] += __shfl_xor_sync(0xffffffffu, G[i], o);
        sq += __shfl_xor_sync(0xffffffffu, sq, o);
    }

    // ---- assignment DP (maximize), layered by popcount; 8 lanes/warp active
    float cost = 0.0f;
    if (j == 0 && valid) {
        float dp[64];
        dp[0] = 0.0f;
#pragma unroll
        for (int kk = 1; kk <= 6; ++kk) {
            const int r = kk - 1;
#pragma unroll
            for (int S = 1; S < 64; ++S) {
                if (__popc((unsigned)S) == kk) {
                    float best = -3.0e38f;
#pragma unroll
                    for (int m = 0; m < 6; ++m)
                        if (S & (1 << m))
                            best = fmaxf(best, dp[S ^ (1 << m)] + G[r * 6 + m]);
                    dp[S] = best;
                }
            }
        }
        cost = sq - 2.0f * dp[63];
    }

    // ---- warp + block reduction, one atomicAdd per block
#pragma unroll
    for (int o = 16; o > 0; o >>= 1)
        cost += __shfl_down_sync(0xffffffffu, cost, o);

    __shared__ float wsum[BLOCK / 32];
    if ((threadIdx.x & 31) == 0) wsum[threadIdx.x >> 5] = cost;
    __syncthreads();
    if (threadIdx.x == 0) {
        float s = 0.0f;
#pragma unroll
        for (int w = 0; w < BLOCK / 32; ++w) s += wsum[w];
        atomicAdd(out, s);
    }
}

extern "C" void kernel_launch(void* const* d_in, const int* in_sizes, int n_in,
                              void* d_out, int out_size)
{
    const float* preds   = (const float*)d_in[0];
    const float* targets = (const float*)d_in[1];
    const int B = in_sizes[0] / 384;   // 6 * 64 floats per batch

    cudaMemsetAsync(d_out, 0, sizeof(float));
    const long long threads = (long long)B * 4;
    const int grid = (int)((threads + BLOCK - 1) / BLOCK);
    emd_kernel<<<grid, BLOCK>>>(preds, targets, (float*)d_out, B);
}